// round 11
// baseline (speedup 1.0000x reference)
#include <cuda_runtime.h>
#include <cuda_fp16.h>
#include <cstdint>
#include <cstddef>

#define BB 256
#define SS 512
#define FF 64
#define HH 1024
#define OO 24

#define NCH0T 34           // W layout L0: 2 input + 32 recurrent chunks
#define NCH1T 64           // L1: 32 + 32
#define STAGE_B 12288      // A 4KB fp16 + B 8KB fp16
#define NST 5
#define SMEM_BYTES (NST * STAGE_B + 512)   // 61952

// ---------------- scratch (device globals; no allocs) ----------------
__device__ __half g_P1h[(size_t)SS * 4 * 32 * 2048];   // h1 perm fp16 [t][bg][chunk][64][32]
__device__ __half g_P2h[(size_t)SS * 4 * 32 * 2048];   // h2 perm fp16
__device__ __half g_Xp[(size_t)SS * 4 * 2 * 2048];     // x perm fp16
__device__ __half g_Xg[(size_t)SS * 4 * 32 * 8192];    // xg fp16 [t][bg][ntile][4][64][32] (shared L0/L1)
__device__ float  g_H2[(size_t)SS * BB * HH];          // h2 flat fp32 [B][S][H] for FC
__device__ float  g_c[BB * HH];                        // cell state fp32
__device__ float  g_part[128 * 256 * 24];              // FC partials
__device__ unsigned g_bar0[4 * SS];
__device__ unsigned g_bar1[4 * SS];
__device__ __half g_Wh0[(size_t)32 * NCH0T * 128 * 32];  // permuted fp16 weights L0
__device__ __half g_Wh1[(size_t)32 * NCH1T * 128 * 32];  // L1

// ---------------- helpers ----------------
// perm: k(p) = 2*((p>>3)&3) + (p&1) + 8*((p>>1)&1) + 16*((p>>2)&1)
__device__ __forceinline__ int kofp(int p) {
    return 2 * ((p >> 3) & 3) + (p & 1) + 8 * ((p >> 1) & 1) + 16 * ((p >> 2) & 1);
}
__device__ __forceinline__ void mma16(float* d,
    unsigned a0, unsigned a1, unsigned a2, unsigned a3, unsigned b0, unsigned b1) {
    asm volatile(
        "mma.sync.aligned.m16n8k16.row.col.f32.f16.f16.f32 "
        "{%0,%1,%2,%3}, {%4,%5,%6,%7}, {%8,%9}, {%0,%1,%2,%3};\n"
        : "+f"(d[0]), "+f"(d[1]), "+f"(d[2]), "+f"(d[3])
        : "r"(a0), "r"(a1), "r"(a2), "r"(a3), "r"(b0), "r"(b1));
}
__device__ __forceinline__ void cpa16(uint32_t dst, const void* src) {
    asm volatile("cp.async.cg.shared.global [%0], [%1], 16;" :: "r"(dst), "l"(src));
}
#define CP_COMMIT() asm volatile("cp.async.commit_group;" ::: "memory")
#define CP_WAIT(n)  asm volatile("cp.async.wait_group %0;" :: "n"(n) : "memory")
#define WAITN(n) do { int _n = (n); \
    if (_n >= 3) CP_WAIT(3); else if (_n == 2) CP_WAIT(2); \
    else if (_n == 1) CP_WAIT(1); else CP_WAIT(0); } while (0)
__device__ __forceinline__ uint32_t smem_u32(const void* p) {
    uint32_t a;
    asm("{ .reg .u64 t; cvta.to.shared.u64 t, %1; cvt.u32.u64 %0, t; }" : "=r"(a) : "l"(p));
    return a;
}
__device__ __forceinline__ float sigm(float x) { return 1.f / (1.f + __expf(-x)); }
__device__ __forceinline__ float tanh_(float x) {
    float a = fabsf(x);
    float e = __expf(-2.f * a);
    return copysignf((1.f - e) / (1.f + e), x);
}

__global__ void bar_reset() {
    int i = blockIdx.x * blockDim.x + threadIdx.x;
    if (i < 4 * SS) { g_bar0[i] = 0; g_bar1[i] = 0; }
}

// weights -> fp16, permuted: dst[((ntile*NCH + c)*128 + j)*32 + p], j = gate*32 + hsub
__global__ void wcvt(const float* __restrict__ Wih, const float* __restrict__ Whh,
                     __half* __restrict__ dst, int KIN, int NCH, size_t total)
{
    size_t d = (size_t)blockIdx.x * 256 + threadIdx.x;
    if (d >= total) return;
    int p = (int)(d & 31);
    int j = (int)((d >> 5) & 127);
    int rest = (int)(d >> 12);
    int c = rest % NCH, ntile = rest / NCH;
    int grow = (j >> 5) * HH + ntile * 32 + (j & 31);
    int k = c * 32 + kofp(p);
    float v = (k < KIN) ? Wih[(size_t)grow * KIN + k]
                        : Whh[(size_t)grow * HH + (k - KIN)];
    dst[d] = __float2half(v);
}

// x -> fp16, permuted chunk layout [t][bg][c(2)][row 64][perm 32]
__global__ void xprep(const float* __restrict__ x, __half* __restrict__ dst)
{
    size_t d = (size_t)blockIdx.x * 256 + threadIdx.x;
    if (d >= (size_t)SS * 4 * 2 * 2048) return;
    int p = (int)(d & 31);
    int row = (int)((d >> 5) & 63);
    int c = (int)((d >> 11) & 1);
    int bg = (int)((d >> 12) & 3);
    int t = (int)(d >> 14);
    int k = c * 32 + kofp(p);
    int b = bg * 64 + row;
    dst[d] = __float2half(x[(size_t)b * SS * FF + (size_t)t * FF + k]);
}

// ---------------- parallel input GEMM: xg = W_ih @ a + bih + bhh (fp16 out) ----------------
// Grid (32 ntiles, 4 bg, SS t); CTA M=64 x N=128, K = KCH chunks of 32.
template <int NCHTOT, int KCH>
__global__ __launch_bounds__(256, 2) void xg_gemm(
    const __half* __restrict__ Ap,      // ((t*4+bg)*KCH + c)*2048
    const __half* __restrict__ Wp,      // (ntile*NCHTOT + c)*4096, chunks 0..KCH-1
    const float* __restrict__ bih, const float* __restrict__ bhh,
    __half* __restrict__ out)           // ((t*4+bg)*32 + ntile)*8192 : [4][64][32]
{
    extern __shared__ char smc[];
    const uint32_t sb = smem_u32(smc);
    const int tid = threadIdx.x, lane = tid & 31, warp = tid >> 5;
    const int g4 = lane >> 2, tig = lane & 3;
    const int wm = warp & 1, wn = warp >> 1;
    const int ntile = blockIdx.x, bg = blockIdx.y, t = blockIdx.z;
    const __half* ab = Ap + (size_t)(t * 4 + bg) * KCH * 2048;

    float2 bias2[4];
#pragma unroll
    for (int nf = 0; nf < 4; nf++) {
        int grow = wn * HH + ntile * 32 + nf * 8 + 2 * tig;
        bias2[nf] = make_float2(bih[grow] + bhh[grow], bih[grow + 1] + bhh[grow + 1]);
    }

    auto issue = [&](int c) {
        int st = c % NST;
        uint32_t sa = sb + st * STAGE_B, sw = sa + 4096;
        cpa16(sa + tid * 16, ab + (size_t)c * 2048 + tid * 8);
        const __half* ws = Wp + ((size_t)ntile * NCHTOT + c) * 4096;
        cpa16(sw + tid * 16, ws + tid * 8);
        cpa16(sw + (tid + 256) * 16, ws + (tid + 256) * 8);
        CP_COMMIT();
    };

    float acc[2][4][4];
#pragma unroll
    for (int mf = 0; mf < 2; mf++)
#pragma unroll
        for (int nf = 0; nf < 4; nf++)
#pragma unroll
            for (int q = 0; q < 4; q++) acc[mf][nf][q] = 0.f;

    constexpr int DEPTH = (KCH < 4) ? KCH : 4;
#pragma unroll
    for (int i = 0; i < DEPTH; i++) issue(i);
    int iss = DEPTH;

    for (int c = 0; c < KCH; ++c) {
        WAITN(iss - (c + 1));
        __syncthreads();
        const char* sa = smc + (c % NST) * STAGE_B;
        const char* sw = sa + 4096;
        uint4 bq[4], alo[2], ahi[2];
#pragma unroll
        for (int nf = 0; nf < 4; nf++)
            bq[nf] = *reinterpret_cast<const uint4*>(sw + (wn * 32 + nf * 8 + g4) * 64 + tig * 16);
#pragma unroll
        for (int mf = 0; mf < 2; mf++) {
            alo[mf] = *reinterpret_cast<const uint4*>(sa + (wm * 32 + mf * 16 + g4) * 64 + tig * 16);
            ahi[mf] = *reinterpret_cast<const uint4*>(sa + (wm * 32 + mf * 16 + g4 + 8) * 64 + tig * 16);
        }
#pragma unroll
        for (int mf = 0; mf < 2; mf++)
#pragma unroll
            for (int nf = 0; nf < 4; nf++) {
                mma16(acc[mf][nf], alo[mf].x, ahi[mf].x, alo[mf].y, ahi[mf].y, bq[nf].x, bq[nf].y);
                mma16(acc[mf][nf], alo[mf].z, ahi[mf].z, alo[mf].w, ahi[mf].w, bq[nf].z, bq[nf].w);
            }
        if (iss < KCH) { issue(iss); ++iss; }
    }

    __half* ob = out + ((size_t)(t * 4 + bg) * 32 + ntile) * 8192 + wn * 2048;
#pragma unroll
    for (int mf = 0; mf < 2; mf++) {
        int r = wm * 32 + mf * 16 + g4;
#pragma unroll
        for (int nf = 0; nf < 4; nf++) {
            int cb = nf * 8 + 2 * tig;
            *reinterpret_cast<__half2*>(ob + r * 32 + cb) =
                __floats2half2_rn(acc[mf][nf][0] + bias2[nf].x, acc[mf][nf][1] + bias2[nf].y);
            *reinterpret_cast<__half2*>(ob + (r + 8) * 32 + cb) =
                __floats2half2_rn(acc[mf][nf][2] + bias2[nf].x, acc[mf][nf][3] + bias2[nf].y);
        }
    }
}

// ---------------- persistent serial LSTM layer: recurrent-only (32 chunks) ----------------
// Grid (32 ntiles, 4 bg), 256 thr. gates = Whh@h[t-1] (GEMM) + xg[t] (preloaded).
template <int NCHTOT, int KOFF>
__global__ __launch_bounds__(256, 1) void lstm_ser(
    const __half* __restrict__ A1p,     // own hperm: ((t*4+bg)*32 + c)*2048
    const __half* __restrict__ Wp,      // recurrent chunks at (ntile*NCHTOT + KOFF + c)
    const __half* __restrict__ Xg,      // ((t*4+bg)*32 + ntile)*8192
    float* __restrict__ cst,
    __half* __restrict__ hperm,
    float* __restrict__ hflat,          // nullptr for layer0
    unsigned* __restrict__ bar)
{
    extern __shared__ char smc[];
    const uint32_t sb = smem_u32(smc);
    const int tid = threadIdx.x, lane = tid & 31, warp = tid >> 5;
    const int g4 = lane >> 2, tig = lane & 3;
    const int wm = warp & 1, wn = warp >> 1;
    const int ntile = blockIdx.x, bg = blockIdx.y;
    const int n0h = ntile * 32, m0 = bg * 64;
    unsigned* barg = bar + bg * SS;

    uint4 fbq[2][4], falo[2][2], fahi[2][2];

    for (int t = 0; t < SS; ++t) {
        float acc[2][4][4];
#pragma unroll
        for (int mf = 0; mf < 2; mf++)
#pragma unroll
            for (int nf = 0; nf < 4; nf++)
#pragma unroll
                for (int q = 0; q < 4; q++) acc[mf][nf][q] = 0.f;

        if (t > 0) {
            const __half* a1b = A1p + (size_t)((t - 1) * 4 + bg) * 32 * 2048;

            auto issue = [&](int c) {
                int st = c % NST;
                uint32_t sa = sb + st * STAGE_B, sw = sa + 4096;
                cpa16(sa + tid * 16, a1b + (size_t)c * 2048 + tid * 8);
                const __half* ws = Wp + ((size_t)ntile * NCHTOT + KOFF + c) * 4096;
                cpa16(sw + tid * 16, ws + tid * 8);
                cpa16(sw + (tid + 256) * 16, ws + (tid + 256) * 8);
                CP_COMMIT();
            };
            auto mmado = [&](int buf) {
#pragma unroll
                for (int mf = 0; mf < 2; mf++)
#pragma unroll
                    for (int nf = 0; nf < 4; nf++) {
                        mma16(acc[mf][nf], falo[buf][mf].x, fahi[buf][mf].x,
                              falo[buf][mf].y, fahi[buf][mf].y, fbq[buf][nf].x, fbq[buf][nf].y);
                        mma16(acc[mf][nf], falo[buf][mf].z, fahi[buf][mf].z,
                              falo[buf][mf].w, fahi[buf][mf].w, fbq[buf][nf].z, fbq[buf][nf].w);
                    }
            };

#define LOADFR(BUF, CH) do {                                                          \
    const char* _sa = smc + ((CH) % NST) * STAGE_B;                                   \
    const char* _sw = _sa + 4096;                                                     \
    _Pragma("unroll")                                                                 \
    for (int nf = 0; nf < 4; nf++)                                                    \
        fbq[BUF][nf] = *reinterpret_cast<const uint4*>(_sw + (wn * 32 + nf * 8 + g4) * 64 + tig * 16); \
    _Pragma("unroll")                                                                 \
    for (int mf = 0; mf < 2; mf++) {                                                  \
        falo[BUF][mf] = *reinterpret_cast<const uint4*>(_sa + (wm * 32 + mf * 16 + g4) * 64 + tig * 16); \
        fahi[BUF][mf] = *reinterpret_cast<const uint4*>(_sa + (wm * 32 + mf * 16 + g4 + 8) * 64 + tig * 16); \
    } } while (0)

            issue(0); issue(1); issue(2); issue(3);
            int iss = 4;
            CP_WAIT(3);
            __syncthreads();
            LOADFR(0, 0);

            for (int c2 = 0; c2 < 16; ++c2) {
                int c = 2 * c2;
                // half-iter A: frags for c in buf0; prep c+1 into buf1
                WAITN(iss - (c + 2));
                __syncthreads();
                LOADFR(1, c + 1);
                if (iss < 32) { issue(iss); ++iss; }
                mmado(0);
                // half-iter B: frags for c+1 in buf1; prep c+2 into buf0
                if (c + 1 < 31) {
                    WAITN(iss - (c + 3));
                    __syncthreads();
                    LOADFR(0, c + 2);
                    if (iss < 32) { issue(iss); ++iss; }
                    mmado(1);
                } else {
                    mmado(1);
                }
            }
#undef LOADFR
        }
        __syncthreads();

        // ---- epilogue: bounce accs through smem ----
        float* sC = (float*)smc;   // [4 gates][64 b][32 h]
#pragma unroll
        for (int mf = 0; mf < 2; mf++) {
            int r = wm * 32 + mf * 16 + g4;
#pragma unroll
            for (int nf = 0; nf < 4; nf++) {
                int col = nf * 8 + 2 * tig;
                *reinterpret_cast<float2*>(&sC[wn * 2048 + r * 32 + col]) =
                    make_float2(acc[mf][nf][0], acc[mf][nf][1]);
                *reinterpret_cast<float2*>(&sC[wn * 2048 + (r + 8) * 32 + col]) =
                    make_float2(acc[mf][nf][2], acc[mf][nf][3]);
            }
        }
        __syncthreads();

        const __half* xgb = Xg + ((size_t)(t * 4 + bg) * 32 + ntile) * 8192;
        __half* permb = hperm + ((size_t)(t * 4 + bg) * 32 + ntile) * 2048;
#pragma unroll
        for (int it = 0; it < 2; it++) {
            int idx4 = it * 256 + tid;
            int bl = idx4 >> 3, q = idx4 & 7, h4 = q * 4;
            uint2 xu[4];
#pragma unroll
            for (int g = 0; g < 4; g++)
                xu[g] = *reinterpret_cast<const uint2*>(xgb + g * 2048 + bl * 32 + h4);
            float4 gi = *reinterpret_cast<float4*>(&sC[0 * 2048 + bl * 32 + h4]);
            float4 gf = *reinterpret_cast<float4*>(&sC[1 * 2048 + bl * 32 + h4]);
            float4 gg = *reinterpret_cast<float4*>(&sC[2 * 2048 + bl * 32 + h4]);
            float4 go = *reinterpret_cast<float4*>(&sC[3 * 2048 + bl * 32 + h4]);
            {
                float2 lo = __half22float2(*reinterpret_cast<__half2*>(&xu[0].x));
                float2 hi = __half22float2(*reinterpret_cast<__half2*>(&xu[0].y));
                gi.x += lo.x; gi.y += lo.y; gi.z += hi.x; gi.w += hi.y;
            }
            {
                float2 lo = __half22float2(*reinterpret_cast<__half2*>(&xu[1].x));
                float2 hi = __half22float2(*reinterpret_cast<__half2*>(&xu[1].y));
                gf.x += lo.x; gf.y += lo.y; gf.z += hi.x; gf.w += hi.y;
            }
            {
                float2 lo = __half22float2(*reinterpret_cast<__half2*>(&xu[2].x));
                float2 hi = __half22float2(*reinterpret_cast<__half2*>(&xu[2].y));
                gg.x += lo.x; gg.y += lo.y; gg.z += hi.x; gg.w += hi.y;
            }
            {
                float2 lo = __half22float2(*reinterpret_cast<__half2*>(&xu[3].x));
                float2 hi = __half22float2(*reinterpret_cast<__half2*>(&xu[3].y));
                go.x += lo.x; go.y += lo.y; go.z += hi.x; go.w += hi.y;
            }
            size_t b = (size_t)(m0 + bl);
            float4 cold = (t == 0) ? make_float4(0.f, 0.f, 0.f, 0.f)
                                   : *reinterpret_cast<float4*>(&cst[b * HH + n0h + h4]);
            float4 cn, hn;
            {
                float ci = sigm(gi.x), cf = sigm(gf.x), cg = tanh_(gg.x), co = sigm(go.x);
                cn.x = cf * cold.x + ci * cg; hn.x = co * tanh_(cn.x);
            }
            {
                float ci = sigm(gi.y), cf = sigm(gf.y), cg = tanh_(gg.y), co = sigm(go.y);
                cn.y = cf * cold.y + ci * cg; hn.y = co * tanh_(cn.y);
            }
            {
                float ci = sigm(gi.z), cf = sigm(gf.z), cg = tanh_(gg.z), co = sigm(go.z);
                cn.z = cf * cold.z + ci * cg; hn.z = co * tanh_(cn.z);
            }
            {
                float ci = sigm(gi.w), cf = sigm(gf.w), cg = tanh_(gg.w), co = sigm(go.w);
                cn.w = cf * cold.w + ci * cg; hn.w = co * tanh_(cn.w);
            }
            *reinterpret_cast<float4*>(&cst[b * HH + n0h + h4]) = cn;
            if (hflat)
                *reinterpret_cast<float4*>(&hflat[(b * SS + (size_t)t) * HH + n0h + h4]) = hn;
            int base2 = ((q >> 2) & 1) * 4 + ((q >> 1) & 1) * 2;
            int pos1 = ((2 * q) & 3) * 8 + base2;
            int pos2 = ((2 * q + 1) & 3) * 8 + base2;
            *reinterpret_cast<__half2*>(permb + bl * 32 + pos1) = __floats2half2_rn(hn.x, hn.y);
            *reinterpret_cast<__half2*>(permb + bl * 32 + pos2) = __floats2half2_rn(hn.z, hn.w);
        }
        __syncthreads();

        if (t + 1 < SS) {
            __threadfence();
            if (tid == 0) {
                atomicAdd(&barg[t], 1u);
                while (*(volatile unsigned*)&barg[t] < 32u) { }
                __threadfence();
            }
            __syncthreads();
        }
    }
}

// ---------------- final FC (fp32 H2 flat) ----------------
__global__ __launch_bounds__(256) void fc_partial(
    const float* __restrict__ H2, const float* __restrict__ fcW,
    float* __restrict__ part)
{
    __shared__ float sH[32 * 132];
    __shared__ float sWf[24 * 132];
    const int tid = threadIdx.x;
    const int btile = blockIdx.x;
    const int kc = blockIdx.y;
    const int bl = tid >> 3, osub = tid & 7;
    const size_t KTOT = (size_t)SS * HH;
    float acc[3] = {0.f, 0.f, 0.f};

    for (int k0 = kc * 4096; k0 < kc * 4096 + 4096; k0 += 128) {
#pragma unroll
        for (int i = 0; i < 4; i++) {
            int idx = tid + i * 256;
            int r = idx >> 5, c4 = idx & 31;
            *reinterpret_cast<float4*>(sH + r * 132 + c4 * 4) =
                *reinterpret_cast<const float4*>(H2 + (size_t)(btile * 32 + r) * KTOT + k0 + c4 * 4);
        }
#pragma unroll
        for (int i = 0; i < 3; i++) {
            int idx = tid + i * 256;
            int r = idx >> 5, c4 = idx & 31;
            *reinterpret_cast<float4*>(sWf + r * 132 + c4 * 4) =
                *reinterpret_cast<const float4*>(fcW + (size_t)r * KTOT + k0 + c4 * 4);
        }
        __syncthreads();
#pragma unroll 8
        for (int kk = 0; kk < 128; kk++) {
            float a = sH[bl * 132 + kk];
            acc[0] += a * sWf[(osub * 3 + 0) * 132 + kk];
            acc[1] += a * sWf[(osub * 3 + 1) * 132 + kk];
            acc[2] += a * sWf[(osub * 3 + 2) * 132 + kk];
        }
        __syncthreads();
    }
    int b = btile * 32 + bl;
#pragma unroll
    for (int j = 0; j < 3; j++)
        part[((size_t)kc * 256 + b) * 24 + osub * 3 + j] = acc[j];
}

__global__ void fc_reduce(const float* __restrict__ part, const float* __restrict__ fcb,
                          float* __restrict__ out)
{
    int id = blockIdx.x * 256 + threadIdx.x;
    if (id >= 256 * 24) return;
    int b = id / 24, o = id % 24;
    float s = fcb[o];
#pragma unroll 8
    for (int kc = 0; kc < 128; kc++) s += part[((size_t)kc * 256 + b) * 24 + o];
    out[(size_t)b * 24 + o] = s;
}

// ---------------- launch (10 graph nodes) ----------------
extern "C" void kernel_launch(void* const* d_in, const int* in_sizes, int n_in,
                              void* d_out, int out_size)
{
    const float* x    = (const float*)d_in[0];
    const float* Wih0 = (const float*)d_in[1];
    const float* Whh0 = (const float*)d_in[2];
    const float* bih0 = (const float*)d_in[3];
    const float* bhh0 = (const float*)d_in[4];
    const float* Wih1 = (const float*)d_in[5];
    const float* Whh1 = (const float*)d_in[6];
    const float* bih1 = (const float*)d_in[7];
    const float* bhh1 = (const float*)d_in[8];
    const float* fcW  = (const float*)d_in[9];
    const float* fcb  = (const float*)d_in[10];

    float *H2p, *cp, *pp;
    __half *p1h, *p2h, *xp, *xg, *wh0, *wh1;
    unsigned *b0p, *b1p;
    cudaGetSymbolAddress((void**)&H2p, g_H2);
    cudaGetSymbolAddress((void**)&cp, g_c);
    cudaGetSymbolAddress((void**)&pp, g_part);
    cudaGetSymbolAddress((void**)&p1h, g_P1h);
    cudaGetSymbolAddress((void**)&p2h, g_P2h);
    cudaGetSymbolAddress((void**)&xp, g_Xp);
    cudaGetSymbolAddress((void**)&xg, g_Xg);
    cudaGetSymbolAddress((void**)&wh0, g_Wh0);
    cudaGetSymbolAddress((void**)&wh1, g_Wh1);
    cudaGetSymbolAddress((void**)&b0p, g_bar0);
    cudaGetSymbolAddress((void**)&b1p, g_bar1);

    cudaFuncSetAttribute(xg_gemm<NCH0T, 2>,  cudaFuncAttributeMaxDynamicSharedMemorySize, SMEM_BYTES);
    cudaFuncSetAttribute(xg_gemm<NCH1T, 32>, cudaFuncAttributeMaxDynamicSharedMemorySize, SMEM_BYTES);
    cudaFuncSetAttribute(lstm_ser<NCH0T, 2>,  cudaFuncAttributeMaxDynamicSharedMemorySize, SMEM_BYTES);
    cudaFuncSetAttribute(lstm_ser<NCH1T, 32>, cudaFuncAttributeMaxDynamicSharedMemorySize, SMEM_BYTES);

    bar_reset<<<8, 256>>>();
    {
        size_t tot0 = (size_t)32 * NCH0T * 128 * 32;
        size_t tot1 = (size_t)32 * NCH1T * 128 * 32;
        wcvt<<<(int)((tot0 + 255) / 256), 256>>>(Wih0, Whh0, wh0, FF, NCH0T, tot0);
        wcvt<<<(int)((tot1 + 255) / 256), 256>>>(Wih1, Whh1, wh1, HH, NCH1T, tot1);
        size_t nx = (size_t)SS * 4 * 2 * 2048;
        xprep<<<(int)((nx + 255) / 256), 256>>>(x, xp);
    }

    dim3 gridg(32, 4, SS);
    dim3 grids(32, 4);
    // layer 0: xg0 = Wih0 @ x + biases (parallel), then recurrent-only serial
    xg_gemm<NCH0T, 2><<<gridg, 256, SMEM_BYTES>>>(xp, wh0, bih0, bhh0, xg);
    lstm_ser<NCH0T, 2><<<grids, 256, SMEM_BYTES>>>(p1h, wh0, xg, cp, p1h, nullptr, b0p);
    // layer 1: xg1 = Wih1 @ h1 + biases (parallel), then recurrent-only serial
    xg_gemm<NCH1T, 32><<<gridg, 256, SMEM_BYTES>>>(p1h, wh1, bih1, bhh1, xg);
    lstm_ser<NCH1T, 32><<<grids, 256, SMEM_BYTES>>>(p2h, wh1, xg, cp, p2h, H2p, b1p);

    fc_partial<<<dim3(8, 128), 256>>>(H2p, fcW, pp);
    fc_reduce<<<24, 256>>>(pp, fcb, (float*)d_out);
}

// round 12
// speedup vs baseline: 1.2211x; 1.2211x over previous
#include <cuda_runtime.h>
#include <cuda_fp16.h>
#include <cstdint>
#include <cstddef>

#define BB 256
#define SS 512
#define FF 64
#define HH 1024
#define OO 24

#define NCH0T 34           // W layout L0: 2 input + 32 recurrent chunks (of K=32)
#define NCH1T 64           // L1: 32 + 32
#define STAGE_B 24576      // superchunk K=64: A 8KB fp16 + B 16KB fp16
#define NST 4
#define SMEM_BYTES (NST * STAGE_B + 512)   // 98816

// ---------------- scratch (device globals; no allocs) ----------------
__device__ __half g_P1h[(size_t)SS * 4 * 32 * 2048];   // h1 perm fp16 [t][bg][chunk][64][32]
__device__ __half g_P2h[(size_t)SS * 4 * 32 * 2048];   // h2 perm fp16
__device__ __half g_Xp[(size_t)SS * 4 * 2 * 2048];     // x perm fp16
__device__ __half g_Xg[(size_t)SS * 4 * 32 * 8192];    // xg fp16 [t][bg][ntile][4][64][32]
__device__ float  g_H2[(size_t)SS * BB * HH];          // h2 flat fp32 [B][S][H] for FC
__device__ float  g_c[BB * HH];                        // cell state fp32
__device__ float  g_part[128 * 256 * 24];              // FC partials
__device__ unsigned g_bar0[4 * SS];
__device__ unsigned g_bar1[4 * SS];
__device__ __half g_Wh0[(size_t)32 * NCH0T * 128 * 32];  // permuted fp16 weights L0
__device__ __half g_Wh1[(size_t)32 * NCH1T * 128 * 32];  // L1

// ---------------- helpers ----------------
// perm: k(p) = 2*((p>>3)&3) + (p&1) + 8*((p>>1)&1) + 16*((p>>2)&1)
__device__ __forceinline__ int kofp(int p) {
    return 2 * ((p >> 3) & 3) + (p & 1) + 8 * ((p >> 1) & 1) + 16 * ((p >> 2) & 1);
}
__device__ __forceinline__ void mma16(float* d,
    unsigned a0, unsigned a1, unsigned a2, unsigned a3, unsigned b0, unsigned b1) {
    asm volatile(
        "mma.sync.aligned.m16n8k16.row.col.f32.f16.f16.f32 "
        "{%0,%1,%2,%3}, {%4,%5,%6,%7}, {%8,%9}, {%0,%1,%2,%3};\n"
        : "+f"(d[0]), "+f"(d[1]), "+f"(d[2]), "+f"(d[3])
        : "r"(a0), "r"(a1), "r"(a2), "r"(a3), "r"(b0), "r"(b1));
}
__device__ __forceinline__ void cpa16(uint32_t dst, const void* src) {
    asm volatile("cp.async.cg.shared.global [%0], [%1], 16;" :: "r"(dst), "l"(src));
}
#define CP_COMMIT() asm volatile("cp.async.commit_group;" ::: "memory")
#define CP_WAIT(n)  asm volatile("cp.async.wait_group %0;" :: "n"(n) : "memory")
#define WAITN(n) do { int _n = (n); \
    if (_n >= 3) CP_WAIT(3); else if (_n == 2) CP_WAIT(2); \
    else if (_n == 1) CP_WAIT(1); else CP_WAIT(0); } while (0)
__device__ __forceinline__ uint32_t smem_u32(const void* p) {
    uint32_t a;
    asm("{ .reg .u64 t; cvta.to.shared.u64 t, %1; cvt.u32.u64 %0, t; }" : "=r"(a) : "l"(p));
    return a;
}
__device__ __forceinline__ float sigm(float x) { return 1.f / (1.f + __expf(-x)); }
__device__ __forceinline__ float tanh_(float x) {
    float a = fabsf(x);
    float e = __expf(-2.f * a);
    return copysignf((1.f - e) / (1.f + e), x);
}

__global__ void bar_reset() {
    int i = blockIdx.x * blockDim.x + threadIdx.x;
    if (i < 4 * SS) { g_bar0[i] = 0; g_bar1[i] = 0; }
}

// weights -> fp16, permuted: dst[((ntile*NCH + c)*128 + j)*32 + p], j = gate*32 + hsub
__global__ void wcvt(const float* __restrict__ Wih, const float* __restrict__ Whh,
                     __half* __restrict__ dst, int KIN, int NCH, size_t total)
{
    size_t d = (size_t)blockIdx.x * 256 + threadIdx.x;
    if (d >= total) return;
    int p = (int)(d & 31);
    int j = (int)((d >> 5) & 127);
    int rest = (int)(d >> 12);
    int c = rest % NCH, ntile = rest / NCH;
    int grow = (j >> 5) * HH + ntile * 32 + (j & 31);
    int k = c * 32 + kofp(p);
    float v = (k < KIN) ? Wih[(size_t)grow * KIN + k]
                        : Whh[(size_t)grow * HH + (k - KIN)];
    dst[d] = __float2half(v);
}

// x -> fp16, permuted chunk layout [t][bg][c(2)][row 64][perm 32]
__global__ void xprep(const float* __restrict__ x, __half* __restrict__ dst)
{
    size_t d = (size_t)blockIdx.x * 256 + threadIdx.x;
    if (d >= (size_t)SS * 4 * 2 * 2048) return;
    int p = (int)(d & 31);
    int row = (int)((d >> 5) & 63);
    int c = (int)((d >> 11) & 1);
    int bg = (int)((d >> 12) & 3);
    int t = (int)(d >> 14);
    int k = c * 32 + kofp(p);
    int b = bg * 64 + row;
    dst[d] = __float2half(x[(size_t)b * SS * FF + (size_t)t * FF + k]);
}

// ---- shared fragment-consume for one superchunk (K=64) ----
// sa: stage base (A 8KB then B 16KB at +8192)
#define CONSUME_SC(SABASE) do {                                                        \
    const char* _sa = (SABASE);                                                        \
    const char* _sw = _sa + 8192;                                                      \
    uint4 bq[2][4], alo[2][2], ahi[2][2];                                              \
    _Pragma("unroll")                                                                  \
    for (int cc = 0; cc < 2; cc++) {                                                   \
        _Pragma("unroll")                                                              \
        for (int nf = 0; nf < 4; nf++)                                                 \
            bq[cc][nf] = *reinterpret_cast<const uint4*>(                              \
                _sw + cc * 8192 + (wn * 32 + nf * 8 + g4) * 64 + tig * 16);            \
        _Pragma("unroll")                                                              \
        for (int mf = 0; mf < 2; mf++) {                                               \
            alo[cc][mf] = *reinterpret_cast<const uint4*>(                             \
                _sa + cc * 4096 + (wm * 32 + mf * 16 + g4) * 64 + tig * 16);           \
            ahi[cc][mf] = *reinterpret_cast<const uint4*>(                             \
                _sa + cc * 4096 + (wm * 32 + mf * 16 + g4 + 8) * 64 + tig * 16);       \
        }                                                                              \
    }                                                                                  \
    _Pragma("unroll")                                                                  \
    for (int cc = 0; cc < 2; cc++)                                                     \
        _Pragma("unroll")                                                              \
        for (int mf = 0; mf < 2; mf++)                                                 \
            _Pragma("unroll")                                                          \
            for (int nf = 0; nf < 4; nf++) {                                           \
                mma16(acc[mf][nf], alo[cc][mf].x, ahi[cc][mf].x,                       \
                      alo[cc][mf].y, ahi[cc][mf].y, bq[cc][nf].x, bq[cc][nf].y);       \
                mma16(acc[mf][nf], alo[cc][mf].z, ahi[cc][mf].z,                       \
                      alo[cc][mf].w, ahi[cc][mf].w, bq[cc][nf].z, bq[cc][nf].w);       \
            }                                                                          \
} while (0)

// ---------------- parallel input GEMM: xg = W_ih @ a + bih + bhh (fp16 out) ----------------
// Grid (32 ntiles, 4 bg, SS t); CTA M=64 x N=128, K = KSC superchunks of 64.
template <int NCHTOT, int KSC>
__global__ __launch_bounds__(256, 1) void xg_gemm(
    const __half* __restrict__ Ap,      // ((t*4+bg)*(2*KSC) + c)*2048
    const __half* __restrict__ Wp,      // (ntile*NCHTOT + c)*4096, chunks 0..2*KSC-1
    const float* __restrict__ bih, const float* __restrict__ bhh,
    __half* __restrict__ out)           // ((t*4+bg)*32 + ntile)*8192 : [4][64][32]
{
    extern __shared__ char smc[];
    const uint32_t sb = smem_u32(smc);
    const int tid = threadIdx.x, lane = tid & 31, warp = tid >> 5;
    const int g4 = lane >> 2, tig = lane & 3;
    const int wm = warp & 1, wn = warp >> 1;
    const int ntile = blockIdx.x, bg = blockIdx.y, t = blockIdx.z;
    const __half* ab = Ap + (size_t)(t * 4 + bg) * (2 * KSC) * 2048;

    float2 bias2[4];
#pragma unroll
    for (int nf = 0; nf < 4; nf++) {
        int grow = wn * HH + ntile * 32 + nf * 8 + 2 * tig;
        bias2[nf] = make_float2(bih[grow] + bhh[grow], bih[grow + 1] + bhh[grow + 1]);
    }

    auto issue = [&](int sc) {
        int st = sc & (NST - 1);
        uint32_t sa = sb + st * STAGE_B, sw = sa + 8192;
        const __half* asrc = ab + (size_t)sc * 4096;
#pragma unroll
        for (int i = 0; i < 2; i++)
            cpa16(sa + (tid + i * 256) * 16, asrc + (tid + i * 256) * 8);
        const __half* ws = Wp + ((size_t)ntile * NCHTOT + 2 * sc) * 4096;
#pragma unroll
        for (int i = 0; i < 4; i++)
            cpa16(sw + (tid + i * 256) * 16, ws + (tid + i * 256) * 8);
        CP_COMMIT();
    };

    float acc[2][4][4];
#pragma unroll
    for (int mf = 0; mf < 2; mf++)
#pragma unroll
        for (int nf = 0; nf < 4; nf++)
#pragma unroll
            for (int q = 0; q < 4; q++) acc[mf][nf][q] = 0.f;

    constexpr int DEPTH = (KSC < 3) ? KSC : 3;
#pragma unroll
    for (int i = 0; i < DEPTH; i++) issue(i);
    int iss = DEPTH;

    for (int sc = 0; sc < KSC; ++sc) {
        WAITN(iss - sc - 1);
        __syncthreads();
        CONSUME_SC(smc + (sc & (NST - 1)) * STAGE_B);
        if (iss < KSC) { issue(iss); ++iss; }
    }

    __half* ob = out + ((size_t)(t * 4 + bg) * 32 + ntile) * 8192 + wn * 2048;
#pragma unroll
    for (int mf = 0; mf < 2; mf++) {
        int r = wm * 32 + mf * 16 + g4;
#pragma unroll
        for (int nf = 0; nf < 4; nf++) {
            int cb = nf * 8 + 2 * tig;
            *reinterpret_cast<__half2*>(ob + r * 32 + cb) =
                __floats2half2_rn(acc[mf][nf][0] + bias2[nf].x, acc[mf][nf][1] + bias2[nf].y);
            *reinterpret_cast<__half2*>(ob + (r + 8) * 32 + cb) =
                __floats2half2_rn(acc[mf][nf][2] + bias2[nf].x, acc[mf][nf][3] + bias2[nf].y);
        }
    }
}

// ---------------- persistent serial LSTM layer: recurrent-only (16 superchunks) ----------------
// Grid (32 ntiles, 4 bg), 256 thr. gates = Whh@h[t-1] (GEMM) + xg[t] (preloaded).
template <int NCHTOT, int KOFF>
__global__ __launch_bounds__(256, 1) void lstm_ser(
    const __half* __restrict__ A1p,     // own hperm: ((t*4+bg)*32 + c)*2048
    const __half* __restrict__ Wp,      // recurrent chunks at (ntile*NCHTOT + KOFF + c)
    const __half* __restrict__ Xg,      // ((t*4+bg)*32 + ntile)*8192
    float* __restrict__ cst,
    __half* __restrict__ hperm,
    float* __restrict__ hflat,          // nullptr for layer0
    unsigned* __restrict__ bar)
{
    extern __shared__ char smc[];
    const uint32_t sb = smem_u32(smc);
    const int tid = threadIdx.x, lane = tid & 31, warp = tid >> 5;
    const int g4 = lane >> 2, tig = lane & 3;
    const int wm = warp & 1, wn = warp >> 1;
    const int ntile = blockIdx.x, bg = blockIdx.y;
    const int n0h = ntile * 32, m0 = bg * 64;
    unsigned* barg = bar + bg * SS;

    for (int t = 0; t < SS; ++t) {
        float acc[2][4][4];
#pragma unroll
        for (int mf = 0; mf < 2; mf++)
#pragma unroll
            for (int nf = 0; nf < 4; nf++)
#pragma unroll
                for (int q = 0; q < 4; q++) acc[mf][nf][q] = 0.f;

        if (t > 0) {
            const __half* a1b = A1p + (size_t)((t - 1) * 4 + bg) * 32 * 2048;

            auto issue = [&](int sc) {
                int st = sc & (NST - 1);
                uint32_t sa = sb + st * STAGE_B, sw = sa + 8192;
                const __half* asrc = a1b + (size_t)sc * 4096;
#pragma unroll
                for (int i = 0; i < 2; i++)
                    cpa16(sa + (tid + i * 256) * 16, asrc + (tid + i * 256) * 8);
                const __half* ws = Wp + ((size_t)ntile * NCHTOT + KOFF + 2 * sc) * 4096;
#pragma unroll
                for (int i = 0; i < 4; i++)
                    cpa16(sw + (tid + i * 256) * 16, ws + (tid + i * 256) * 8);
                CP_COMMIT();
            };

            issue(0); issue(1); issue(2);
            int iss = 3;
            for (int sc = 0; sc < 16; ++sc) {
                WAITN(iss - sc - 1);
                __syncthreads();
                CONSUME_SC(smc + (sc & (NST - 1)) * STAGE_B);
                if (iss < 16) { issue(iss); ++iss; }
            }
        }
        __syncthreads();

        // ---- epilogue: bounce accs through smem ----
        float* sC = (float*)smc;   // [4 gates][64 b][32 h]
#pragma unroll
        for (int mf = 0; mf < 2; mf++) {
            int r = wm * 32 + mf * 16 + g4;
#pragma unroll
            for (int nf = 0; nf < 4; nf++) {
                int col = nf * 8 + 2 * tig;
                *reinterpret_cast<float2*>(&sC[wn * 2048 + r * 32 + col]) =
                    make_float2(acc[mf][nf][0], acc[mf][nf][1]);
                *reinterpret_cast<float2*>(&sC[wn * 2048 + (r + 8) * 32 + col]) =
                    make_float2(acc[mf][nf][2], acc[mf][nf][3]);
            }
        }
        __syncthreads();

        const __half* xgb = Xg + ((size_t)(t * 4 + bg) * 32 + ntile) * 8192;
        __half* permb = hperm + ((size_t)(t * 4 + bg) * 32 + ntile) * 2048;
#pragma unroll
        for (int it = 0; it < 2; it++) {
            int idx4 = it * 256 + tid;
            int bl = idx4 >> 3, q = idx4 & 7, h4 = q * 4;
            uint2 xu[4];
#pragma unroll
            for (int g = 0; g < 4; g++)
                xu[g] = *reinterpret_cast<const uint2*>(xgb + g * 2048 + bl * 32 + h4);
            float4 gi = *reinterpret_cast<float4*>(&sC[0 * 2048 + bl * 32 + h4]);
            float4 gf = *reinterpret_cast<float4*>(&sC[1 * 2048 + bl * 32 + h4]);
            float4 gg = *reinterpret_cast<float4*>(&sC[2 * 2048 + bl * 32 + h4]);
            float4 go = *reinterpret_cast<float4*>(&sC[3 * 2048 + bl * 32 + h4]);
            {
                float2 lo = __half22float2(*reinterpret_cast<__half2*>(&xu[0].x));
                float2 hi = __half22float2(*reinterpret_cast<__half2*>(&xu[0].y));
                gi.x += lo.x; gi.y += lo.y; gi.z += hi.x; gi.w += hi.y;
            }
            {
                float2 lo = __half22float2(*reinterpret_cast<__half2*>(&xu[1].x));
                float2 hi = __half22float2(*reinterpret_cast<__half2*>(&xu[1].y));
                gf.x += lo.x; gf.y += lo.y; gf.z += hi.x; gf.w += hi.y;
            }
            {
                float2 lo = __half22float2(*reinterpret_cast<__half2*>(&xu[2].x));
                float2 hi = __half22float2(*reinterpret_cast<__half2*>(&xu[2].y));
                gg.x += lo.x; gg.y += lo.y; gg.z += hi.x; gg.w += hi.y;
            }
            {
                float2 lo = __half22float2(*reinterpret_cast<__half2*>(&xu[3].x));
                float2 hi = __half22float2(*reinterpret_cast<__half2*>(&xu[3].y));
                go.x += lo.x; go.y += lo.y; go.z += hi.x; go.w += hi.y;
            }
            size_t b = (size_t)(m0 + bl);
            float4 cold = (t == 0) ? make_float4(0.f, 0.f, 0.f, 0.f)
                                   : *reinterpret_cast<float4*>(&cst[b * HH + n0h + h4]);
            float4 cn, hn;
            {
                float ci = sigm(gi.x), cf = sigm(gf.x), cg = tanh_(gg.x), co = sigm(go.x);
                cn.x = cf * cold.x + ci * cg; hn.x = co * tanh_(cn.x);
            }
            {
                float ci = sigm(gi.y), cf = sigm(gf.y), cg = tanh_(gg.y), co = sigm(go.y);
                cn.y = cf * cold.y + ci * cg; hn.y = co * tanh_(cn.y);
            }
            {
                float ci = sigm(gi.z), cf = sigm(gf.z), cg = tanh_(gg.z), co = sigm(go.z);
                cn.z = cf * cold.z + ci * cg; hn.z = co * tanh_(cn.z);
            }
            {
                float ci = sigm(gi.w), cf = sigm(gf.w), cg = tanh_(gg.w), co = sigm(go.w);
                cn.w = cf * cold.w + ci * cg; hn.w = co * tanh_(cn.w);
            }
            *reinterpret_cast<float4*>(&cst[b * HH + n0h + h4]) = cn;
            if (hflat)
                *reinterpret_cast<float4*>(&hflat[(b * SS + (size_t)t) * HH + n0h + h4]) = hn;
            int base2 = ((q >> 2) & 1) * 4 + ((q >> 1) & 1) * 2;
            int pos1 = ((2 * q) & 3) * 8 + base2;
            int pos2 = ((2 * q + 1) & 3) * 8 + base2;
            *reinterpret_cast<__half2*>(permb + bl * 32 + pos1) = __floats2half2_rn(hn.x, hn.y);
            *reinterpret_cast<__half2*>(permb + bl * 32 + pos2) = __floats2half2_rn(hn.z, hn.w);
        }
        __syncthreads();

        if (t + 1 < SS) {
            __threadfence();
            if (tid == 0) {
                atomicAdd(&barg[t], 1u);
                while (*(volatile unsigned*)&barg[t] < 32u) { }
                __threadfence();
            }
            __syncthreads();
        }
    }
}

// ---------------- final FC (fp32 H2 flat) ----------------
__global__ __launch_bounds__(256) void fc_partial(
    const float* __restrict__ H2, const float* __restrict__ fcW,
    float* __restrict__ part)
{
    __shared__ float sH[32 * 132];
    __shared__ float sWf[24 * 132];
    const int tid = threadIdx.x;
    const int btile = blockIdx.x;
    const int kc = blockIdx.y;
    const int bl = tid >> 3, osub = tid & 7;
    const size_t KTOT = (size_t)SS * HH;
    float acc[3] = {0.f, 0.f, 0.f};

    for (int k0 = kc * 4096; k0 < kc * 4096 + 4096; k0 += 128) {
#pragma unroll
        for (int i = 0; i < 4; i++) {
            int idx = tid + i * 256;
            int r = idx >> 5, c4 = idx & 31;
            *reinterpret_cast<float4*>(sH + r * 132 + c4 * 4) =
                *reinterpret_cast<const float4*>(H2 + (size_t)(btile * 32 + r) * KTOT + k0 + c4 * 4);
        }
#pragma unroll
        for (int i = 0; i < 3; i++) {
            int idx = tid + i * 256;
            int r = idx >> 5, c4 = idx & 31;
            *reinterpret_cast<float4*>(sWf + r * 132 + c4 * 4) =
                *reinterpret_cast<const float4*>(fcW + (size_t)r * KTOT + k0 + c4 * 4);
        }
        __syncthreads();
#pragma unroll 8
        for (int kk = 0; kk < 128; kk++) {
            float a = sH[bl * 132 + kk];
            acc[0] += a * sWf[(osub * 3 + 0) * 132 + kk];
            acc[1] += a * sWf[(osub * 3 + 1) * 132 + kk];
            acc[2] += a * sWf[(osub * 3 + 2) * 132 + kk];
        }
        __syncthreads();
    }
    int b = btile * 32 + bl;
#pragma unroll
    for (int j = 0; j < 3; j++)
        part[((size_t)kc * 256 + b) * 24 + osub * 3 + j] = acc[j];
}

__global__ void fc_reduce(const float* __restrict__ part, const float* __restrict__ fcb,
                          float* __restrict__ out)
{
    int id = blockIdx.x * 256 + threadIdx.x;
    if (id >= 256 * 24) return;
    int b = id / 24, o = id % 24;
    float s = fcb[o];
#pragma unroll 8
    for (int kc = 0; kc < 128; kc++) s += part[((size_t)kc * 256 + b) * 24 + o];
    out[(size_t)b * 24 + o] = s;
}

// ---------------- launch (10 graph nodes) ----------------
extern "C" void kernel_launch(void* const* d_in, const int* in_sizes, int n_in,
                              void* d_out, int out_size)
{
    const float* x    = (const float*)d_in[0];
    const float* Wih0 = (const float*)d_in[1];
    const float* Whh0 = (const float*)d_in[2];
    const float* bih0 = (const float*)d_in[3];
    const float* bhh0 = (const float*)d_in[4];
    const float* Wih1 = (const float*)d_in[5];
    const float* Whh1 = (const float*)d_in[6];
    const float* bih1 = (const float*)d_in[7];
    const float* bhh1 = (const float*)d_in[8];
    const float* fcW  = (const float*)d_in[9];
    const float* fcb  = (const float*)d_in[10];

    float *H2p, *cp, *pp;
    __half *p1h, *p2h, *xp, *xg, *wh0, *wh1;
    unsigned *b0p, *b1p;
    cudaGetSymbolAddress((void**)&H2p, g_H2);
    cudaGetSymbolAddress((void**)&cp, g_c);
    cudaGetSymbolAddress((void**)&pp, g_part);
    cudaGetSymbolAddress((void**)&p1h, g_P1h);
    cudaGetSymbolAddress((void**)&p2h, g_P2h);
    cudaGetSymbolAddress((void**)&xp, g_Xp);
    cudaGetSymbolAddress((void**)&xg, g_Xg);
    cudaGetSymbolAddress((void**)&wh0, g_Wh0);
    cudaGetSymbolAddress((void**)&wh1, g_Wh1);
    cudaGetSymbolAddress((void**)&b0p, g_bar0);
    cudaGetSymbolAddress((void**)&b1p, g_bar1);

    cudaFuncSetAttribute(xg_gemm<NCH0T, 1>,  cudaFuncAttributeMaxDynamicSharedMemorySize, SMEM_BYTES);
    cudaFuncSetAttribute(xg_gemm<NCH1T, 16>, cudaFuncAttributeMaxDynamicSharedMemorySize, SMEM_BYTES);
    cudaFuncSetAttribute(lstm_ser<NCH0T, 2>,  cudaFuncAttributeMaxDynamicSharedMemorySize, SMEM_BYTES);
    cudaFuncSetAttribute(lstm_ser<NCH1T, 32>, cudaFuncAttributeMaxDynamicSharedMemorySize, SMEM_BYTES);

    bar_reset<<<8, 256>>>();
    {
        size_t tot0 = (size_t)32 * NCH0T * 128 * 32;
        size_t tot1 = (size_t)32 * NCH1T * 128 * 32;
        wcvt<<<(int)((tot0 + 255) / 256), 256>>>(Wih0, Whh0, wh0, FF, NCH0T, tot0);
        wcvt<<<(int)((tot1 + 255) / 256), 256>>>(Wih1, Whh1, wh1, HH, NCH1T, tot1);
        size_t nx = (size_t)SS * 4 * 2 * 2048;
        xprep<<<(int)((nx + 255) / 256), 256>>>(x, xp);
    }

    dim3 gridg(32, 4, SS);
    dim3 grids(32, 4);
    // layer 0: xg0 = Wih0 @ x + biases (1 superchunk), then recurrent-only serial
    xg_gemm<NCH0T, 1><<<gridg, 256, SMEM_BYTES>>>(xp, wh0, bih0, bhh0, xg);
    lstm_ser<NCH0T, 2><<<grids, 256, SMEM_BYTES>>>(p1h, wh0, xg, cp, p1h, nullptr, b0p);
    // layer 1: xg1 = Wih1 @ h1 + biases (16 superchunks), then recurrent-only serial
    xg_gemm<NCH1T, 16><<<gridg, 256, SMEM_BYTES>>>(p1h, wh1, bih1, bhh1, xg);
    lstm_ser<NCH1T, 32><<<grids, 256, SMEM_BYTES>>>(p2h, wh1, xg, cp, p2h, H2p, b1p);

    fc_partial<<<dim3(8, 128), 256>>>(H2p, fcW, pp);
    fc_reduce<<<24, 256>>>(pp, fcb, (float*)d_out);
}

// round 13
// speedup vs baseline: 1.2281x; 1.0057x over previous
#include <cuda_runtime.h>
#include <cuda_fp16.h>
#include <cstdint>
#include <cstddef>

#define BB 256
#define SS 512
#define FF 64
#define HH 1024
#define OO 24

#define NCH0T 34           // W layout L0: 2 input + 32 recurrent chunks (of K=32)
#define NCH1T 64           // L1: 32 + 32
#define STAGE_B 49152      // K=128 stage: A 16KB + B 32KB
#define NST 3
#define SMEM_BYTES (NST * STAGE_B)   // 147456

// ---------------- scratch (device globals; no allocs) ----------------
__device__ __half g_P1h[(size_t)SS * 4 * 32 * 2048];   // h1 perm fp16 [t][bg][chunk][64][32]
__device__ __half g_P2h[(size_t)SS * 4 * 32 * 2048];   // h2 perm fp16
__device__ __half g_Xp[(size_t)SS * 4 * 2 * 2048];     // x perm fp16
__device__ __half g_Xg[(size_t)SS * 4 * 32 * 8192];    // xg fp16 [t][bg][ntile][gate][64][32]
__device__ float  g_H2[(size_t)SS * BB * HH];          // h2 flat fp32 [B][S][H] for FC
__device__ float  g_c[BB * HH];                        // cell state fp32 (thread-swizzled)
__device__ float  g_part[128 * 256 * 24];              // FC partials
__device__ unsigned g_bar0[4 * SS];
__device__ unsigned g_bar1[4 * SS];
__device__ __half g_Wh0[(size_t)32 * NCH0T * 128 * 32];  // permuted fp16 weights L0
__device__ __half g_Wh1[(size_t)32 * NCH1T * 128 * 32];  // L1

// ---------------- helpers ----------------
// k-perm within 32: k(p) = 2*((p>>3)&3) + (p&1) + 8*((p>>1)&1) + 16*((p>>2)&1)
__device__ __forceinline__ int kofp(int p) {
    return 2 * ((p >> 3) & 3) + (p & 1) + 8 * ((p >> 1) & 1) + 16 * ((p >> 2) & 1);
}
__device__ __forceinline__ void mma16(float* d,
    unsigned a0, unsigned a1, unsigned a2, unsigned a3, unsigned b0, unsigned b1) {
    asm volatile(
        "mma.sync.aligned.m16n8k16.row.col.f32.f16.f16.f32 "
        "{%0,%1,%2,%3}, {%4,%5,%6,%7}, {%8,%9}, {%0,%1,%2,%3};\n"
        : "+f"(d[0]), "+f"(d[1]), "+f"(d[2]), "+f"(d[3])
        : "r"(a0), "r"(a1), "r"(a2), "r"(a3), "r"(b0), "r"(b1));
}
__device__ __forceinline__ void cpa16(uint32_t dst, const void* src) {
    asm volatile("cp.async.cg.shared.global [%0], [%1], 16;" :: "r"(dst), "l"(src));
}
#define CP_COMMIT() asm volatile("cp.async.commit_group;" ::: "memory")
#define CP_WAIT(n)  asm volatile("cp.async.wait_group %0;" :: "n"(n) : "memory")
#define WAITN(n) do { int _n = (n); \
    if (_n >= 2) CP_WAIT(2); else if (_n == 1) CP_WAIT(1); else CP_WAIT(0); } while (0)
__device__ __forceinline__ uint32_t smem_u32(const void* p) {
    uint32_t a;
    asm("{ .reg .u64 t; cvta.to.shared.u64 t, %1; cvt.u32.u64 %0, t; }" : "=r"(a) : "l"(p));
    return a;
}
__device__ __forceinline__ float sigm(float x) { return 1.f / (1.f + __expf(-x)); }
__device__ __forceinline__ float tanh_(float x) {
    float a = fabsf(x);
    float e = __expf(-2.f * a);
    return copysignf((1.f - e) / (1.f + e), x);
}

// consume CN chunks (K=32 each) of one stage. Stage layout: A at +cc*4096, B at 16384+cc*8192.
template <int CN>
__device__ __forceinline__ void consume_sc(const char* sa, float acc[2][4][4],
                                           int wm, int wn, int g4, int tig) {
#pragma unroll
    for (int cc = 0; cc < CN; cc++) {
        const char* A = sa + cc * 4096;
        const char* B = sa + 16384 + cc * 8192;
        uint4 bq[4], alo[2], ahi[2];
#pragma unroll
        for (int nf = 0; nf < 4; nf++)
            bq[nf] = *reinterpret_cast<const uint4*>(B + (wn * 32 + nf * 8 + g4) * 64 + tig * 16);
#pragma unroll
        for (int mf = 0; mf < 2; mf++) {
            alo[mf] = *reinterpret_cast<const uint4*>(A + (wm * 32 + mf * 16 + g4) * 64 + tig * 16);
            ahi[mf] = *reinterpret_cast<const uint4*>(A + (wm * 32 + mf * 16 + g4 + 8) * 64 + tig * 16);
        }
#pragma unroll
        for (int mf = 0; mf < 2; mf++)
#pragma unroll
            for (int nf = 0; nf < 4; nf++) {
                mma16(acc[mf][nf], alo[mf].x, ahi[mf].x, alo[mf].y, ahi[mf].y, bq[nf].x, bq[nf].y);
                mma16(acc[mf][nf], alo[mf].z, ahi[mf].z, alo[mf].w, ahi[mf].w, bq[nf].z, bq[nf].w);
            }
    }
}

__global__ void bar_reset() {
    int i = blockIdx.x * blockDim.x + threadIdx.x;
    if (i < 4 * SS) { g_bar0[i] = 0; g_bar1[i] = 0; }
}

// weights -> fp16, permuted. NEW j layout: j = (hsub>>3)*32 + gate*8 + (hsub&7)
// i.e. gate = (j>>3)&3, hsub = (j>>5)*8 + (j&7).
__global__ void wcvt(const float* __restrict__ Wih, const float* __restrict__ Whh,
                     __half* __restrict__ dst, int KIN, int NCH, size_t total)
{
    size_t d = (size_t)blockIdx.x * 256 + threadIdx.x;
    if (d >= total) return;
    int p = (int)(d & 31);
    int j = (int)((d >> 5) & 127);
    int rest = (int)(d >> 12);
    int c = rest % NCH, ntile = rest / NCH;
    int gate = (j >> 3) & 3;
    int hsub = (j >> 5) * 8 + (j & 7);
    int grow = gate * HH + ntile * 32 + hsub;
    int k = c * 32 + kofp(p);
    float v = (k < KIN) ? Wih[(size_t)grow * KIN + k]
                        : Whh[(size_t)grow * HH + (k - KIN)];
    dst[d] = __float2half(v);
}

// x -> fp16, permuted chunk layout [t][bg][c(2)][row 64][perm 32]
__global__ void xprep(const float* __restrict__ x, __half* __restrict__ dst)
{
    size_t d = (size_t)blockIdx.x * 256 + threadIdx.x;
    if (d >= (size_t)SS * 4 * 2 * 2048) return;
    int p = (int)(d & 31);
    int row = (int)((d >> 5) & 63);
    int c = (int)((d >> 11) & 1);
    int bg = (int)((d >> 12) & 3);
    int t = (int)(d >> 14);
    int k = c * 32 + kofp(p);
    int b = bg * 64 + row;
    dst[d] = __float2half(x[(size_t)b * SS * FF + (size_t)t * FF + k]);
}

// ---------------- parallel input GEMM: xg = W_ih @ a + bih + bhh (fp16 out) ----------------
// Grid (32 ntiles, 4 bg, SS t); CTA M=64 x N=128 (gates in-warp), K = KC32 chunks of 32.
template <int NCHTOT, int KC32>
__global__ __launch_bounds__(256, 1) void xg_gemm(
    const __half* __restrict__ Ap,      // ((t*4+bg)*KC32 + c)*2048
    const __half* __restrict__ Wp,      // (ntile*NCHTOT + c)*4096
    const float* __restrict__ bih, const float* __restrict__ bhh,
    __half* __restrict__ out)           // ((t*4+bg)*32 + ntile)*8192 : [gate][64][32]
{
    constexpr int S = (KC32 + 3) / 4;
    constexpr int TAIL = KC32 - 4 * (KC32 / 4);
    extern __shared__ char smc[];
    const uint32_t sb = smem_u32(smc);
    const int tid = threadIdx.x, lane = tid & 31, warp = tid >> 5;
    const int g4 = lane >> 2, tig = lane & 3;
    const int wm = warp & 1, wn = warp >> 1;
    const int ntile = blockIdx.x, bg = blockIdx.y, t = blockIdx.z;
    const __half* ab = Ap + (size_t)(t * 4 + bg) * KC32 * 2048;

    float2 bias2[4];
#pragma unroll
    for (int nf = 0; nf < 4; nf++) {
        int grow = nf * HH + ntile * 32 + wn * 8 + 2 * tig;
        bias2[nf] = make_float2(bih[grow] + bhh[grow], bih[grow + 1] + bhh[grow + 1]);
    }

    auto issue = [&](int s) {
        int st = s % NST;
        uint32_t sa = sb + st * STAGE_B;
        int cbase = 4 * s;
        int cn = KC32 - cbase; if (cn > 4) cn = 4;
        const __half* asrc = ab + (size_t)cbase * 2048;
        for (int i = 0; i < cn; i++)
            cpa16(sa + (tid + i * 256) * 16, asrc + (tid + i * 256) * 8);
        const __half* ws = Wp + ((size_t)ntile * NCHTOT + cbase) * 4096;
        for (int i = 0; i < 2 * cn; i++)
            cpa16(sa + 16384 + (tid + i * 256) * 16, ws + (tid + i * 256) * 8);
        CP_COMMIT();
    };

    float acc[2][4][4];
#pragma unroll
    for (int mf = 0; mf < 2; mf++)
#pragma unroll
        for (int nf = 0; nf < 4; nf++)
#pragma unroll
            for (int q = 0; q < 4; q++) acc[mf][nf][q] = 0.f;

    issue(0);
    if (S > 1) issue(1);
    int iss = (S > 1) ? 2 : 1;

    for (int s = 0; s < S; ++s) {
        WAITN(iss - s - 1);
        __syncthreads();
        const char* sa = smc + (s % NST) * STAGE_B;
        if (TAIL > 0 && s == S - 1) consume_sc<(TAIL > 0) ? TAIL : 4>(sa, acc, wm, wn, g4, tig);
        else                        consume_sc<4>(sa, acc, wm, wn, g4, tig);
        if (iss < S) { issue(iss); ++iss; }
    }

    __half* ob = out + ((size_t)(t * 4 + bg) * 32 + ntile) * 8192;
#pragma unroll
    for (int mf = 0; mf < 2; mf++)
#pragma unroll
        for (int rh = 0; rh < 2; rh++) {
            int row = wm * 32 + mf * 16 + g4 + rh * 8;
#pragma unroll
            for (int nf = 0; nf < 4; nf++) {
                *reinterpret_cast<__half2*>(ob + nf * 2048 + row * 32 + wn * 8 + 2 * tig) =
                    __floats2half2_rn(acc[mf][nf][rh * 2] + bias2[nf].x,
                                      acc[mf][nf][rh * 2 + 1] + bias2[nf].y);
            }
        }
}

// ---------------- persistent serial LSTM layer: recurrent-only (8 K128 stages) ----------------
// Grid (32 ntiles, 4 bg), 256 thr. gates = Whh@h[t-1] (GEMM) + xg[t] (preloaded, biases baked).
template <int NCHTOT, int KOFF>
__global__ __launch_bounds__(256, 1) void lstm_ser(
    const __half* __restrict__ A1p,     // own hperm: ((t*4+bg)*32 + c)*2048
    const __half* __restrict__ Wp,      // recurrent chunks at (ntile*NCHTOT + KOFF + c)
    const __half* __restrict__ Xg,      // ((t*4+bg)*32 + ntile)*8192 [gate][64][32]
    float* __restrict__ cst,            // thread-swizzled: ((bg*32+ntile)*256 + tid)*8
    __half* __restrict__ hperm,
    float* __restrict__ hflat,          // nullptr for layer0
    unsigned* __restrict__ bar)
{
    extern __shared__ char smc[];
    const uint32_t sb = smem_u32(smc);
    const int tid = threadIdx.x, lane = tid & 31, warp = tid >> 5;
    const int g4 = lane >> 2, tig = lane & 3;
    const int wm = warp & 1, wn = warp >> 1;
    const int ntile = blockIdx.x, bg = blockIdx.y;
    const int n0h = ntile * 32, m0 = bg * 64;
    unsigned* barg = bar + bg * SS;
    float* cthr = cst + ((size_t)((bg * 32 + ntile) * 256 + tid)) * 8;
    const int pbase = tig * 8 + (wn >> 1) * 4 + (wn & 1) * 2;   // perm pos of col pair

    for (int t = 0; t < SS; ++t) {
        // prefetch xg for this step (biases already baked in)
        const __half* xgb = Xg + ((size_t)(t * 4 + bg) * 32 + ntile) * 8192;
        unsigned xg2[2][2][4];
#pragma unroll
        for (int mf = 0; mf < 2; mf++)
#pragma unroll
            for (int rh = 0; rh < 2; rh++) {
                int row = wm * 32 + mf * 16 + g4 + rh * 8;
#pragma unroll
                for (int nf = 0; nf < 4; nf++)
                    xg2[mf][rh][nf] = *reinterpret_cast<const unsigned*>(
                        xgb + nf * 2048 + row * 32 + wn * 8 + 2 * tig);
            }

        float acc[2][4][4];
#pragma unroll
        for (int mf = 0; mf < 2; mf++)
#pragma unroll
            for (int nf = 0; nf < 4; nf++)
#pragma unroll
                for (int q = 0; q < 4; q++) acc[mf][nf][q] = 0.f;

        if (t > 0) {
            const __half* a1b = A1p + (size_t)((t - 1) * 4 + bg) * 32 * 2048;
            auto issue = [&](int s) {
                int st = s % NST;
                uint32_t sa = sb + st * STAGE_B;
                const __half* asrc = a1b + (size_t)s * 8192;
#pragma unroll
                for (int i = 0; i < 4; i++)
                    cpa16(sa + (tid + i * 256) * 16, asrc + (tid + i * 256) * 8);
                const __half* ws = Wp + ((size_t)ntile * NCHTOT + KOFF + 4 * s) * 4096;
#pragma unroll
                for (int i = 0; i < 8; i++)
                    cpa16(sa + 16384 + (tid + i * 256) * 16, ws + (tid + i * 256) * 8);
                CP_COMMIT();
            };
            issue(0); issue(1);
            int iss = 2;
            for (int s = 0; s < 8; ++s) {
                WAITN(iss - s - 1);
                __syncthreads();
                consume_sc<4>(smc + (s % NST) * STAGE_B, acc, wm, wn, g4, tig);
                if (iss < 8) { issue(iss); ++iss; }
            }
        }

        // ---- all-register epilogue ----
        float cvals[8];
        if (t > 0) {
            float4 v0 = *reinterpret_cast<float4*>(cthr);
            float4 v1 = *reinterpret_cast<float4*>(cthr + 4);
            cvals[0] = v0.x; cvals[1] = v0.y; cvals[2] = v0.z; cvals[3] = v0.w;
            cvals[4] = v1.x; cvals[5] = v1.y; cvals[6] = v1.z; cvals[7] = v1.w;
        } else {
#pragma unroll
            for (int i = 0; i < 8; i++) cvals[i] = 0.f;
        }

        __half* permb = hperm + ((size_t)(t * 4 + bg) * 32 + ntile) * 2048;
#pragma unroll
        for (int mf = 0; mf < 2; mf++)
#pragma unroll
            for (int rh = 0; rh < 2; rh++) {
                int row = wm * 32 + mf * 16 + g4 + rh * 8;
                float2 xi = __half22float2(*reinterpret_cast<__half2*>(&xg2[mf][rh][0]));
                float2 xf = __half22float2(*reinterpret_cast<__half2*>(&xg2[mf][rh][1]));
                float2 xgg = __half22float2(*reinterpret_cast<__half2*>(&xg2[mf][rh][2]));
                float2 xo = __half22float2(*reinterpret_cast<__half2*>(&xg2[mf][rh][3]));
                float gi0 = acc[mf][0][rh * 2]     + xi.x;
                float gi1 = acc[mf][0][rh * 2 + 1] + xi.y;
                float gf0 = acc[mf][1][rh * 2]     + xf.x;
                float gf1 = acc[mf][1][rh * 2 + 1] + xf.y;
                float gg0 = acc[mf][2][rh * 2]     + xgg.x;
                float gg1 = acc[mf][2][rh * 2 + 1] + xgg.y;
                float go0 = acc[mf][3][rh * 2]     + xo.x;
                float go1 = acc[mf][3][rh * 2 + 1] + xo.y;
                int ci = mf * 4 + rh * 2;
                float cn0 = sigm(gf0) * cvals[ci]     + sigm(gi0) * tanh_(gg0);
                float cn1 = sigm(gf1) * cvals[ci + 1] + sigm(gi1) * tanh_(gg1);
                float hn0 = sigm(go0) * tanh_(cn0);
                float hn1 = sigm(go1) * tanh_(cn1);
                cvals[ci] = cn0; cvals[ci + 1] = cn1;
                *reinterpret_cast<__half2*>(permb + row * 32 + pbase) = __floats2half2_rn(hn0, hn1);
                if (hflat)
                    *reinterpret_cast<float2*>(
                        &hflat[((size_t)(m0 + row) * SS + (size_t)t) * HH + n0h + wn * 8 + 2 * tig]) =
                        make_float2(hn0, hn1);
            }
        *reinterpret_cast<float4*>(cthr) = make_float4(cvals[0], cvals[1], cvals[2], cvals[3]);
        *reinterpret_cast<float4*>(cthr + 4) = make_float4(cvals[4], cvals[5], cvals[6], cvals[7]);

        __syncthreads();
        if (t + 1 < SS) {
            __threadfence();
            if (tid == 0) {
                atomicAdd(&barg[t], 1u);
                while (*(volatile unsigned*)&barg[t] < 32u) { }
                __threadfence();
            }
            __syncthreads();
        }
    }
}

// ---------------- final FC (fp32 H2 flat) ----------------
__global__ __launch_bounds__(256) void fc_partial(
    const float* __restrict__ H2, const float* __restrict__ fcW,
    float* __restrict__ part)
{
    __shared__ float sH[32 * 132];
    __shared__ float sWf[24 * 132];
    const int tid = threadIdx.x;
    const int btile = blockIdx.x;
    const int kc = blockIdx.y;
    const int bl = tid >> 3, osub = tid & 7;
    const size_t KTOT = (size_t)SS * HH;
    float acc[3] = {0.f, 0.f, 0.f};

    for (int k0 = kc * 4096; k0 < kc * 4096 + 4096; k0 += 128) {
#pragma unroll
        for (int i = 0; i < 4; i++) {
            int idx = tid + i * 256;
            int r = idx >> 5, c4 = idx & 31;
            *reinterpret_cast<float4*>(sH + r * 132 + c4 * 4) =
                *reinterpret_cast<const float4*>(H2 + (size_t)(btile * 32 + r) * KTOT + k0 + c4 * 4);
        }
#pragma unroll
        for (int i = 0; i < 3; i++) {
            int idx = tid + i * 256;
            int r = idx >> 5, c4 = idx & 31;
            *reinterpret_cast<float4*>(sWf + r * 132 + c4 * 4) =
                *reinterpret_cast<const float4*>(fcW + (size_t)r * KTOT + k0 + c4 * 4);
        }
        __syncthreads();
#pragma unroll 8
        for (int kk = 0; kk < 128; kk++) {
            float a = sH[bl * 132 + kk];
            acc[0] += a * sWf[(osub * 3 + 0) * 132 + kk];
            acc[1] += a * sWf[(osub * 3 + 1) * 132 + kk];
            acc[2] += a * sWf[(osub * 3 + 2) * 132 + kk];
        }
        __syncthreads();
    }
    int b = btile * 32 + bl;
#pragma unroll
    for (int j = 0; j < 3; j++)
        part[((size_t)kc * 256 + b) * 24 + osub * 3 + j] = acc[j];
}

__global__ void fc_reduce(const float* __restrict__ part, const float* __restrict__ fcb,
                          float* __restrict__ out)
{
    int id = blockIdx.x * 256 + threadIdx.x;
    if (id >= 256 * 24) return;
    int b = id / 24, o = id % 24;
    float s = fcb[o];
#pragma unroll 8
    for (int kc = 0; kc < 128; kc++) s += part[((size_t)kc * 256 + b) * 24 + o];
    out[(size_t)b * 24 + o] = s;
}

// ---------------- launch (10 graph nodes) ----------------
extern "C" void kernel_launch(void* const* d_in, const int* in_sizes, int n_in,
                              void* d_out, int out_size)
{
    const float* x    = (const float*)d_in[0];
    const float* Wih0 = (const float*)d_in[1];
    const float* Whh0 = (const float*)d_in[2];
    const float* bih0 = (const float*)d_in[3];
    const float* bhh0 = (const float*)d_in[4];
    const float* Wih1 = (const float*)d_in[5];
    const float* Whh1 = (const float*)d_in[6];
    const float* bih1 = (const float*)d_in[7];
    const float* bhh1 = (const float*)d_in[8];
    const float* fcW  = (const float*)d_in[9];
    const float* fcb  = (const float*)d_in[10];

    float *H2p, *cp, *pp;
    __half *p1h, *p2h, *xp, *xg, *wh0, *wh1;
    unsigned *b0p, *b1p;
    cudaGetSymbolAddress((void**)&H2p, g_H2);
    cudaGetSymbolAddress((void**)&cp, g_c);
    cudaGetSymbolAddress((void**)&pp, g_part);
    cudaGetSymbolAddress((void**)&p1h, g_P1h);
    cudaGetSymbolAddress((void**)&p2h, g_P2h);
    cudaGetSymbolAddress((void**)&xp, g_Xp);
    cudaGetSymbolAddress((void**)&xg, g_Xg);
    cudaGetSymbolAddress((void**)&wh0, g_Wh0);
    cudaGetSymbolAddress((void**)&wh1, g_Wh1);
    cudaGetSymbolAddress((void**)&b0p, g_bar0);
    cudaGetSymbolAddress((void**)&b1p, g_bar1);

    cudaFuncSetAttribute(xg_gemm<NCH0T, 2>,   cudaFuncAttributeMaxDynamicSharedMemorySize, SMEM_BYTES);
    cudaFuncSetAttribute(xg_gemm<NCH1T, 32>,  cudaFuncAttributeMaxDynamicSharedMemorySize, SMEM_BYTES);
    cudaFuncSetAttribute(lstm_ser<NCH0T, 2>,  cudaFuncAttributeMaxDynamicSharedMemorySize, SMEM_BYTES);
    cudaFuncSetAttribute(lstm_ser<NCH1T, 32>, cudaFuncAttributeMaxDynamicSharedMemorySize, SMEM_BYTES);

    bar_reset<<<8, 256>>>();
    {
        size_t tot0 = (size_t)32 * NCH0T * 128 * 32;
        size_t tot1 = (size_t)32 * NCH1T * 128 * 32;
        wcvt<<<(int)((tot0 + 255) / 256), 256>>>(Wih0, Whh0, wh0, FF, NCH0T, tot0);
        wcvt<<<(int)((tot1 + 255) / 256), 256>>>(Wih1, Whh1, wh1, HH, NCH1T, tot1);
        size_t nx = (size_t)SS * 4 * 2 * 2048;
        xprep<<<(int)((nx + 255) / 256), 256>>>(x, xp);
    }

    dim3 gridg(32, 4, SS);
    dim3 grids(32, 4);
    // layer 0: xg0 = Wih0 @ x + biases (2 chunks), then recurrent-only serial
    xg_gemm<NCH0T, 2><<<gridg, 256, SMEM_BYTES>>>(xp, wh0, bih0, bhh0, xg);
    lstm_ser<NCH0T, 2><<<grids, 256, SMEM_BYTES>>>(p1h, wh0, xg, cp, p1h, nullptr, b0p);
    // layer 1: xg1 = Wih1 @ h1 + biases (32 chunks), then recurrent-only serial
    xg_gemm<NCH1T, 32><<<gridg, 256, SMEM_BYTES>>>(p1h, wh1, bih1, bhh1, xg);
    lstm_ser<NCH1T, 32><<<grids, 256, SMEM_BYTES>>>(p2h, wh1, xg, cp, p2h, H2p, b1p);

    fc_partial<<<dim3(8, 128), 256>>>(H2p, fcW, pp);
    fc_reduce<<<24, 256>>>(pp, fcb, (float*)d_out);
}